// round 1
// baseline (speedup 1.0000x reference)
#include <cuda_runtime.h>
#include <cuda_bf16.h>
#include <math.h>

// ---------------- problem constants ----------------
#define LNUM 12
#define H    768
#define NH   12
#define DH   64
#define FF   3072
#define VOC  30522
#define TT   256
#define BB   32
#define KK   35
#define START_TAG 33
#define END_TAG   34
#define ROWS (BB*TT)            // 8192

// ---------------- device scratch (allocation-free) ----------------
__device__ float g_x   [ROWS*H];
__device__ float g_q   [ROWS*H];
__device__ float g_k   [ROWS*H];
__device__ float g_v   [ROWS*H];
__device__ float g_ctx [ROWS*H];
__device__ float g_tmp [ROWS*H];
__device__ float g_ff  [ROWS*FF];
__device__ float g_logits[ROWS*KK];
__device__ float g_fwd [BB];
__device__ float g_gold[BB];
__device__ int   g_bp  [(TT-1)*BB*KK];

// ---------------- embedding + layernorm ----------------
__global__ void embed_ln_kernel(const int* __restrict__ ids,
                                const int* __restrict__ seg,
                                const float* __restrict__ wemb,
                                const float* __restrict__ pemb,
                                const float* __restrict__ temb,
                                const float* __restrict__ gam,
                                const float* __restrict__ bet,
                                float* __restrict__ X)
{
    int r = blockIdx.x;          // 0..8191
    int t = r % TT;
    __shared__ float buf[H];
    __shared__ float red[256];
    int tid = threadIdx.x;
    int id = ids[r], sg = seg[r];
    float lsum = 0.f, lsq = 0.f;
    for (int j = tid; j < H; j += 256) {
        float v = wemb[id*H + j] + pemb[t*H + j] + temb[sg*H + j];
        buf[j] = v; lsum += v; lsq += v*v;
    }
    red[tid] = lsum; __syncthreads();
    for (int s = 128; s > 0; s >>= 1) { if (tid < s) red[tid] += red[tid+s]; __syncthreads(); }
    float mean = red[0] / (float)H; __syncthreads();
    red[tid] = lsq; __syncthreads();
    for (int s = 128; s > 0; s >>= 1) { if (tid < s) red[tid] += red[tid+s]; __syncthreads(); }
    float var = red[0] / (float)H - mean*mean;
    float rstd = rsqrtf(var + 1e-12f);
    for (int j = tid; j < H; j += 256)
        X[r*H + j] = (buf[j] - mean) * rstd * gam[j] + bet[j];
}

// ---------------- residual add + layernorm ----------------
__global__ void add_ln_kernel(const float* __restrict__ X,
                              const float* __restrict__ D,
                              const float* __restrict__ gam,
                              const float* __restrict__ bet,
                              float* __restrict__ Y)
{
    int r = blockIdx.x;
    __shared__ float buf[H];
    __shared__ float red[256];
    int tid = threadIdx.x;
    float lsum = 0.f, lsq = 0.f;
    for (int j = tid; j < H; j += 256) {
        float v = X[r*H + j] + D[r*H + j];
        buf[j] = v; lsum += v; lsq += v*v;
    }
    red[tid] = lsum; __syncthreads();
    for (int s = 128; s > 0; s >>= 1) { if (tid < s) red[tid] += red[tid+s]; __syncthreads(); }
    float mean = red[0] / (float)H; __syncthreads();
    red[tid] = lsq; __syncthreads();
    for (int s = 128; s > 0; s >>= 1) { if (tid < s) red[tid] += red[tid+s]; __syncthreads(); }
    float var = red[0] / (float)H - mean*mean;
    float rstd = rsqrtf(var + 1e-12f);
    for (int j = tid; j < H; j += 256)
        Y[r*H + j] = (buf[j] - mean) * rstd * gam[j] + bet[j];
}

// ---------------- fp32 SGEMM: C = A(MxK) * B(KxN) + bias, optional exact GELU ----
// all dims multiples of tile sizes (M=8192, N in {768,3072}, K in {768,3072})
__global__ __launch_bounds__(256, 2)
void sgemm_bias(const float* __restrict__ A, const float* __restrict__ B,
                const float* __restrict__ bias, float* __restrict__ C,
                int M, int N, int K, int act)
{
    const int BM = 128, BN = 128, BK = 8;
    __shared__ float As[BK][BM];
    __shared__ float Bs[BK][BN];
    int tid = threadIdx.x;                 // 256 threads
    int bx = blockIdx.x, by = blockIdx.y;
    int row0 = by * BM, col0 = bx * BN;
    int aRow = tid >> 1, aCol = (tid & 1) * 4;
    int bRow = tid >> 5, bCol = (tid & 31) * 4;
    int tx = tid & 15, ty = tid >> 4;
    float acc[8][8];
    #pragma unroll
    for (int i = 0; i < 8; i++)
        #pragma unroll
        for (int j = 0; j < 8; j++) acc[i][j] = 0.f;

    const float* Aptr = A + (size_t)(row0 + aRow) * K + aCol;
    const float* Bptr = B + (size_t)bRow * N + col0 + bCol;

    for (int k0 = 0; k0 < K; k0 += BK) {
        float4 a = *(const float4*)Aptr;
        As[aCol+0][aRow] = a.x; As[aCol+1][aRow] = a.y;
        As[aCol+2][aRow] = a.z; As[aCol+3][aRow] = a.w;
        float4 bv = *(const float4*)Bptr;
        *(float4*)&Bs[bRow][bCol] = bv;
        __syncthreads();
        #pragma unroll
        for (int k = 0; k < BK; k++) {
            float ra[8], rb[8];
            #pragma unroll
            for (int i = 0; i < 8; i++) ra[i] = As[k][ty*8 + i];
            #pragma unroll
            for (int j = 0; j < 8; j++) rb[j] = Bs[k][tx*8 + j];
            #pragma unroll
            for (int i = 0; i < 8; i++)
                #pragma unroll
                for (int j = 0; j < 8; j++)
                    acc[i][j] += ra[i] * rb[j];
        }
        __syncthreads();
        Aptr += BK;
        Bptr += (size_t)BK * N;
    }

    #pragma unroll
    for (int i = 0; i < 8; i++) {
        size_t r = row0 + ty*8 + i;
        #pragma unroll
        for (int j = 0; j < 8; j += 4) {
            int c = col0 + tx*8 + j;
            float4 o;
            o.x = acc[i][j+0] + bias[c+0];
            o.y = acc[i][j+1] + bias[c+1];
            o.z = acc[i][j+2] + bias[c+2];
            o.w = acc[i][j+3] + bias[c+3];
            if (act == 1) {
                o.x = 0.5f*o.x*(1.0f + erff(o.x*0.70710678118654752f));
                o.y = 0.5f*o.y*(1.0f + erff(o.y*0.70710678118654752f));
                o.z = 0.5f*o.z*(1.0f + erff(o.z*0.70710678118654752f));
                o.w = 0.5f*o.w*(1.0f + erff(o.w*0.70710678118654752f));
            }
            *(float4*)&C[r*N + c] = o;
        }
    }
}

// ---------------- fused attention (per b,h block; K,V in smem) ----------------
#define ATT_LD 65
#define ATT_SMEM_FLOATS (2*TT*ATT_LD + DH + TT + TT)
__global__ void attention_kernel(const float* __restrict__ Q,
                                 const float* __restrict__ Kin,
                                 const float* __restrict__ Vin,
                                 const int* __restrict__ mask,
                                 float* __restrict__ O)
{
    extern __shared__ float sm[];
    float* Ks    = sm;                    // TT*65
    float* Vs    = Ks + TT*ATT_LD;        // TT*65
    float* qrow  = Vs + TT*ATT_LD;        // 64
    float* probs = qrow + DH;             // 256
    float* red   = probs + TT;            // 256

    int h = blockIdx.x, b = blockIdx.y;
    int tid = threadIdx.x;                // 256
    const float* Kb = Kin + (size_t)(b*TT)*H + h*DH;
    const float* Vb = Vin + (size_t)(b*TT)*H + h*DH;
    for (int idx = tid; idx < TT*DH; idx += 256) {
        int s = idx >> 6, d = idx & 63;
        Ks[s*ATT_LD + d] = Kb[(size_t)s*H + d];
        Vs[s*ATT_LD + d] = Vb[(size_t)s*H + d];
    }
    float mbias = (mask[b*TT + tid] != 0) ? 0.f : -10000.f;
    __syncthreads();

    const float scale = 0.125f;           // 1/sqrt(64)
    int dd = tid & 63, part = tid >> 6;

    for (int t = 0; t < TT; t++) {
        if (tid < DH) qrow[tid] = Q[(size_t)(b*TT + t)*H + h*DH + tid];
        __syncthreads();
        // scores: one key per thread
        float dot = 0.f;
        #pragma unroll 16
        for (int d = 0; d < DH; d++) dot += qrow[d] * Ks[tid*ATT_LD + d];
        float sc = dot * scale + mbias;
        red[tid] = sc; __syncthreads();
        for (int s = 128; s > 0; s >>= 1) {
            if (tid < s) { float o = red[tid+s]; if (o > red[tid]) red[tid] = o; }
            __syncthreads();
        }
        float mx = red[0]; __syncthreads();
        float p = expf(sc - mx);
        probs[tid] = p;
        red[tid] = p; __syncthreads();
        for (int s = 128; s > 0; s >>= 1) { if (tid < s) red[tid] += red[tid+s]; __syncthreads(); }
        float inv = 1.f / red[0]; __syncthreads();
        // context: thread = (d, quarter-of-keys)
        float acc = 0.f;
        int sBeg = part * 64;
        #pragma unroll 16
        for (int ss = 0; ss < 64; ss++)
            acc += probs[sBeg + ss] * Vs[(sBeg + ss)*ATT_LD + dd];
        red[tid] = acc; __syncthreads();
        if (tid < DH) {
            float o = (red[tid] + red[tid+64] + red[tid+128] + red[tid+192]) * inv;
            O[(size_t)(b*TT + t)*H + h*DH + tid] = o;
        }
        __syncthreads();
    }
}

// ---------------- head GEMM (N=35) ----------------
__global__ void head_gemm(const float* __restrict__ X, const float* __restrict__ W,
                          const float* __restrict__ bias, float* __restrict__ Lg)
{
    int r = blockIdx.x;
    __shared__ float xs[H];
    for (int j = threadIdx.x; j < H; j += blockDim.x) xs[j] = X[(size_t)r*H + j];
    __syncthreads();
    if (threadIdx.x < KK) {
        int k = threadIdx.x;
        float s = bias[k];
        for (int j = 0; j < H; j++) s += xs[j] * W[j*KK + k];
        Lg[r*KK + k] = s;
    }
}

// ---------------- CRF forward + gold score ----------------
__global__ void crf_forward_kernel(const float* __restrict__ logits,
                                   const int* __restrict__ mask,
                                   const int* __restrict__ labels,
                                   const float* __restrict__ trans,
                                   float* __restrict__ fwd, float* __restrict__ gold)
{
    int b = blockIdx.x;
    __shared__ float tr[KK*KK];
    __shared__ float alpha[KK];
    int tid = threadIdx.x;   // 64
    for (int i = tid; i < KK*KK; i += 64) tr[i] = trans[i];
    __syncthreads();
    int j = tid;
    if (j < KK) alpha[j] = tr[START_TAG*KK + j] + logits[(size_t)(b*TT)*KK + j];
    __syncthreads();
    for (int t = 1; t < TT; t++) {
        float nv = 0.f;
        if (j < KK) {
            float mxv = -1e30f;
            for (int i = 0; i < KK; i++) { float v = alpha[i] + tr[i*KK + j]; if (v > mxv) mxv = v; }
            float s = 0.f;
            for (int i = 0; i < KK; i++) s += expf(alpha[i] + tr[i*KK + j] - mxv);
            nv = mxv + logf(s) + logits[(size_t)(b*TT + t)*KK + j];
        }
        int keep = (mask[b*TT + t] != 0);
        __syncthreads();
        if (j < KK && keep) alpha[j] = nv;
        __syncthreads();
    }
    if (j == 0) {
        float mxv = -1e30f;
        for (int i = 0; i < KK; i++) { float v = alpha[i] + tr[i*KK + END_TAG]; if (v > mxv) mxv = v; }
        float s = 0.f;
        for (int i = 0; i < KK; i++) s += expf(alpha[i] + tr[i*KK + END_TAG] - mxv);
        fwd[b] = mxv + logf(s);

        // gold score
        int tag0 = labels[b*TT + 0];
        float sc = tr[START_TAG*KK + tag0] + logits[(size_t)(b*TT)*KK + tag0];
        int prev = tag0;
        int lengths = 0;
        for (int t = 0; t < TT; t++) lengths += (mask[b*TT + t] != 0);
        for (int t = 1; t < TT; t++) {
            int tg = labels[b*TT + t];
            float mt = (mask[b*TT + t] != 0) ? 1.f : 0.f;
            sc += (tr[prev*KK + tg] + logits[(size_t)(b*TT + t)*KK + tg]) * mt;
            prev = tg;
        }
        int li = lengths - 1; if (li < 0) li = 0; if (li > TT-1) li = TT-1;
        int last_tag = labels[b*TT + li];
        sc += tr[last_tag*KK + END_TAG];
        gold[b] = sc;
    }
}

__global__ void loss_kernel(const float* __restrict__ fwd, const float* __restrict__ gold,
                            float* __restrict__ out)
{
    if (threadIdx.x == 0 && blockIdx.x == 0) {
        float s = 0.f;
        for (int b = 0; b < BB; b++) s += fwd[b] - gold[b];
        out[0] = s / (float)BB;
    }
}

// ---------------- Viterbi ----------------
__global__ void viterbi_kernel(const float* __restrict__ logits,
                               const int* __restrict__ mask,
                               const float* __restrict__ trans,
                               int* __restrict__ bps,
                               float* __restrict__ out)   // out[1 + b*TT + t]
{
    int b = blockIdx.x;
    __shared__ float tr[KK*KK];
    __shared__ float alpha[KK];
    int tid = threadIdx.x;   // 64
    for (int i = tid; i < KK*KK; i += 64) tr[i] = trans[i];
    __syncthreads();
    int j = tid;
    if (j < KK) alpha[j] = tr[START_TAG*KK + j] + logits[(size_t)(b*TT)*KK + j];
    __syncthreads();
    for (int t = 1; t < TT; t++) {
        float vmax = -1e30f; int bp = 0;
        if (j < KK) {
            for (int i = 0; i < KK; i++) {
                float v = alpha[i] + tr[i*KK + j];
                if (v > vmax) { vmax = v; bp = i; }     // first-max tiebreak (ascending i)
            }
            vmax += logits[(size_t)(b*TT + t)*KK + j];
        }
        int keep = (mask[b*TT + t] != 0);
        __syncthreads();
        if (j < KK) {
            if (keep) alpha[j] = vmax;
            bps[((t-1)*BB + b)*KK + j] = keep ? bp : j;
        }
        __syncthreads();
    }
    if (j == 0) {
        float best = -1e30f; int cur = 0;
        for (int i = 0; i < KK; i++) {
            float v = alpha[i] + tr[i*KK + END_TAG];
            if (v > best) { best = v; cur = i; }
        }
        out[1 + b*TT + (TT-1)] = (float)cur;
        for (int tt = TT-2; tt >= 0; tt--) {
            cur = bps[(tt*BB + b)*KK + cur];
            out[1 + b*TT + tt] = (float)cur;
        }
    }
}

// ---------------- host orchestration ----------------
extern "C" void kernel_launch(void* const* d_in, const int* in_sizes, int n_in,
                              void* d_out, int out_size)
{
    const int*   ids  = (const int*)  d_in[0];
    const int*   msk  = (const int*)  d_in[1];
    const int*   seg  = (const int*)  d_in[2];
    const int*   lab  = (const int*)  d_in[3];
    const float* wemb = (const float*)d_in[4];
    const float* pemb = (const float*)d_in[5];
    const float* temb = (const float*)d_in[6];
    const float* eg   = (const float*)d_in[7];
    const float* eb   = (const float*)d_in[8];
    const float* Wq   = (const float*)d_in[9];
    const float* bq   = (const float*)d_in[10];
    const float* Wk   = (const float*)d_in[11];
    const float* bk   = (const float*)d_in[12];
    const float* Wv   = (const float*)d_in[13];
    const float* bv   = (const float*)d_in[14];
    const float* Wo   = (const float*)d_in[15];
    const float* bo   = (const float*)d_in[16];
    const float* ln1g = (const float*)d_in[17];
    const float* ln1b = (const float*)d_in[18];
    const float* W1   = (const float*)d_in[19];
    const float* b1   = (const float*)d_in[20];
    const float* W2   = (const float*)d_in[21];
    const float* b2   = (const float*)d_in[22];
    const float* ln2g = (const float*)d_in[23];
    const float* ln2b = (const float*)d_in[24];
    const float* Wh   = (const float*)d_in[25];
    const float* bh   = (const float*)d_in[26];
    const float* trn  = (const float*)d_in[27];
    float* out = (float*)d_out;

    float *px, *pq, *pk, *pv, *pctx, *ptmp, *pff, *plog, *pfwd, *pgold;
    int* pbp;
    cudaGetSymbolAddress((void**)&px,   g_x);
    cudaGetSymbolAddress((void**)&pq,   g_q);
    cudaGetSymbolAddress((void**)&pk,   g_k);
    cudaGetSymbolAddress((void**)&pv,   g_v);
    cudaGetSymbolAddress((void**)&pctx, g_ctx);
    cudaGetSymbolAddress((void**)&ptmp, g_tmp);
    cudaGetSymbolAddress((void**)&pff,  g_ff);
    cudaGetSymbolAddress((void**)&plog, g_logits);
    cudaGetSymbolAddress((void**)&pfwd, g_fwd);
    cudaGetSymbolAddress((void**)&pgold,g_gold);
    cudaGetSymbolAddress((void**)&pbp,  g_bp);

    const size_t att_smem = ATT_SMEM_FLOATS * sizeof(float);
    cudaFuncSetAttribute(attention_kernel,
                         cudaFuncAttributeMaxDynamicSharedMemorySize, (int)att_smem);

    // embedding + LN
    embed_ln_kernel<<<ROWS, 256>>>(ids, seg, wemb, pemb, temb, eg, eb, px);

    dim3 g768(H/128, ROWS/128);    // (6, 64)
    dim3 gFF(FF/128, ROWS/128);    // (24, 64)

    for (int l = 0; l < LNUM; l++) {
        const float* wq = Wq + (size_t)l*H*H;  const float* bql = bq + (size_t)l*H;
        const float* wk = Wk + (size_t)l*H*H;  const float* bkl = bk + (size_t)l*H;
        const float* wv = Wv + (size_t)l*H*H;  const float* bvl = bv + (size_t)l*H;
        const float* wo = Wo + (size_t)l*H*H;  const float* bol = bo + (size_t)l*H;

        sgemm_bias<<<g768, 256>>>(px, wq, bql, pq, ROWS, H, H, 0);
        sgemm_bias<<<g768, 256>>>(px, wk, bkl, pk, ROWS, H, H, 0);
        sgemm_bias<<<g768, 256>>>(px, wv, bvl, pv, ROWS, H, H, 0);

        attention_kernel<<<dim3(NH, BB), 256, att_smem>>>(pq, pk, pv, msk, pctx);

        sgemm_bias<<<g768, 256>>>(pctx, wo, bol, ptmp, ROWS, H, H, 0);
        add_ln_kernel<<<ROWS, 256>>>(px, ptmp, ln1g + (size_t)l*H, ln1b + (size_t)l*H, px);

        sgemm_bias<<<gFF, 256>>>(px, W1 + (size_t)l*H*FF, b1 + (size_t)l*FF, pff,
                                 ROWS, FF, H, 1 /*gelu*/);
        sgemm_bias<<<g768, 256>>>(pff, W2 + (size_t)l*FF*H, b2 + (size_t)l*H, ptmp,
                                  ROWS, H, FF, 0);
        add_ln_kernel<<<ROWS, 256>>>(px, ptmp, ln2g + (size_t)l*H, ln2b + (size_t)l*H, px);
    }

    head_gemm<<<ROWS, 128>>>(px, Wh, bh, plog);
    crf_forward_kernel<<<BB, 64>>>(plog, msk, lab, trn, pfwd, pgold);
    loss_kernel<<<1, 32>>>(pfwd, pgold, out);
    viterbi_kernel<<<BB, 64>>>(plog, msk, trn, pbp, out);
}

// round 4
// speedup vs baseline: 1.7126x; 1.7126x over previous
#include <cuda_runtime.h>
#include <cuda_bf16.h>
#include <math.h>
#include <stdint.h>

// ---------------- problem constants ----------------
#define LNUM 12
#define H    768
#define NH   12
#define DH   64
#define FF   3072
#define TT   256
#define BB   32
#define KK   35
#define START_TAG 33
#define END_TAG   34
#define ROWS (BB*TT)            // 8192
#define QKVN 2304               // fused q|k|v output width

// ---------------- device scratch (allocation-free) ----------------
__device__ float g_x   [ROWS*H];
__device__ float g_ctx [ROWS*H];
__device__ float g_tmp [ROWS*H];
__device__ float g_ff  [ROWS*FF];
__device__ float g_qkv [ROWS*QKVN];
__device__ float g_logits[ROWS*KK];
__device__ float g_fwd [BB];
__device__ float g_gold[BB];
__device__ int   g_bp  [(TT-1)*BB*KK];

__device__ __nv_bfloat16 g_ah[ROWS*FF];   // activation hi (max K=3072)
__device__ __nv_bfloat16 g_al[ROWS*FF];   // activation lo
__device__ __nv_bfloat16 g_wqkv_h[LNUM*QKVN*H], g_wqkv_l[LNUM*QKVN*H];
__device__ __nv_bfloat16 g_wo_h[LNUM*H*H],      g_wo_l[LNUM*H*H];
__device__ __nv_bfloat16 g_w1_h[LNUM*FF*H],     g_w1_l[LNUM*FF*H];
__device__ __nv_bfloat16 g_w2_h[LNUM*H*FF],     g_w2_l[LNUM*H*FF];
__device__ float g_bqkv[LNUM*QKVN];

// ---------------- PTX helpers (sm_80-compatible only) ----------------
__device__ __forceinline__ uint32_t smem_u32(const void* p) {
    uint32_t a;
    asm("{ .reg .u64 t; cvta.to.shared.u64 t, %1; cvt.u32.u64 %0, t; }" : "=r"(a) : "l"(p));
    return a;
}
__device__ __forceinline__ void cpasync16(uint32_t s, const void* g) {
    asm volatile("cp.async.cg.shared.global [%0], [%1], 16;" :: "r"(s), "l"(g));
}
__device__ __forceinline__ void ldsm4(uint32_t& r0, uint32_t& r1, uint32_t& r2, uint32_t& r3,
                                      uint32_t addr) {
    asm volatile("ldmatrix.sync.aligned.m8n8.x4.shared.b16 {%0,%1,%2,%3}, [%4];"
                 : "=r"(r0), "=r"(r1), "=r"(r2), "=r"(r3) : "r"(addr));
}
__device__ __forceinline__ void mma16816(float* d, uint32_t a0, uint32_t a1, uint32_t a2,
                                         uint32_t a3, uint32_t b0, uint32_t b1) {
    asm volatile(
        "mma.sync.aligned.m16n8k16.row.col.f32.bf16.bf16.f32 "
        "{%0,%1,%2,%3}, {%4,%5,%6,%7}, {%8,%9}, {%0,%1,%2,%3};"
        : "+f"(d[0]), "+f"(d[1]), "+f"(d[2]), "+f"(d[3])
        : "r"(a0), "r"(a1), "r"(a2), "r"(a3), "r"(b0), "r"(b1));
}

// ---------------- split fp32 -> (hi, lo) bf16 ----------------
__global__ void asplit(const float* __restrict__ X,
                       __nv_bfloat16* __restrict__ hi, __nv_bfloat16* __restrict__ lo,
                       int n4)
{
    int i = blockIdx.x * blockDim.x + threadIdx.x;
    if (i >= n4) return;
    float4 v = ((const float4*)X)[i];
    __nv_bfloat16 h0 = __float2bfloat16(v.x);
    __nv_bfloat16 h1 = __float2bfloat16(v.y);
    __nv_bfloat16 h2 = __float2bfloat16(v.z);
    __nv_bfloat16 h3 = __float2bfloat16(v.w);
    __nv_bfloat16 l0 = __float2bfloat16(v.x - __bfloat162float(h0));
    __nv_bfloat16 l1 = __float2bfloat16(v.y - __bfloat162float(h1));
    __nv_bfloat16 l2 = __float2bfloat16(v.z - __bfloat162float(h2));
    __nv_bfloat16 l3 = __float2bfloat16(v.w - __bfloat162float(h3));
    uint2 hp, lp;
    hp.x = (uint32_t)__bfloat16_as_ushort(h0) | ((uint32_t)__bfloat16_as_ushort(h1) << 16);
    hp.y = (uint32_t)__bfloat16_as_ushort(h2) | ((uint32_t)__bfloat16_as_ushort(h3) << 16);
    lp.x = (uint32_t)__bfloat16_as_ushort(l0) | ((uint32_t)__bfloat16_as_ushort(l1) << 16);
    lp.y = (uint32_t)__bfloat16_as_ushort(l2) | ((uint32_t)__bfloat16_as_ushort(l3) << 16);
    ((uint2*)hi)[i] = hp;
    ((uint2*)lo)[i] = lp;
}

// transpose + split: W[K,N] fp32 (row-major) -> out[N,K] bf16 hi/lo
__global__ void wsplit(const float* __restrict__ W,
                       __nv_bfloat16* __restrict__ hi, __nv_bfloat16* __restrict__ lo,
                       int K, int N, size_t w_lstride, size_t o_lstride)
{
    int l = blockIdx.z;
    const float* Wl = W + (size_t)l * w_lstride;
    __shared__ float t[32][33];
    int k0 = blockIdx.x * 32, n0 = blockIdx.y * 32;
    for (int i = threadIdx.y; i < 32; i += 8)
        t[i][threadIdx.x] = Wl[(size_t)(k0 + i) * N + n0 + threadIdx.x];
    __syncthreads();
    for (int i = threadIdx.y; i < 32; i += 8) {
        int n = n0 + i, k = k0 + threadIdx.x;
        float v = t[threadIdx.x][i];
        __nv_bfloat16 h = __float2bfloat16(v);
        __nv_bfloat16 lw = __float2bfloat16(v - __bfloat162float(h));
        size_t o = (size_t)l * o_lstride + (size_t)n * K + k;
        hi[o] = h; lo[o] = lw;
    }
}

__global__ void pack_bias(const float* __restrict__ bq, const float* __restrict__ bk,
                          const float* __restrict__ bv, float* __restrict__ bqkv)
{
    int l = blockIdx.x;
    for (int j = threadIdx.x; j < H; j += blockDim.x) {
        bqkv[l*QKVN + j]        = bq[l*H + j];
        bqkv[l*QKVN + H + j]    = bk[l*H + j];
        bqkv[l*QKVN + 2*H + j]  = bv[l*H + j];
    }
}

// ---------------- mma.sync split-bf16 GEMM ----------------
// C[M,N] = (Ah+Al)[M,K] @ (Bh+Bl)[N,K]^T + bias   (lo*lo dropped)
// tile 128x128x32 per CTA, 8 warps (2x4), warp 64x32, 4-stage cp.async.
#define BM 128
#define BN 128
#define BKC 32
#define STAGES 4
#define STAGE_A (BM*128)                 // 16384 B (hi|lo packed per row)
#define STAGE_BYTES (STAGE_A + BN*128)   // 32768
#define GEMM_SMEM (STAGES*STAGE_BYTES)   // 131072

#define LOAD_STAGE(st, kc) do {                                                   \
    uint32_t sA_ = sbase + (uint32_t)(st)*STAGE_BYTES;                            \
    uint32_t sB_ = sA_ + STAGE_A;                                                 \
    _Pragma("unroll")                                                             \
    for (int i_ = 0; i_ < 4; i_++) {                                              \
        int e_ = tid + i_*256;                                                    \
        int r_ = e_ >> 3, c_ = e_ & 7;                                            \
        uint32_t off_ = (uint32_t)(r_*128) + (((c_*16) ^ ((r_&7)<<4)));           \
        const __nv_bfloat16* src_ = ((c_<4)? Ah : Al)                             \
            + (size_t)(m0 + r_)*K + (kc) + (c_&3)*8;                              \
        cpasync16(sA_ + off_, src_);                                              \
    }                                                                             \
    _Pragma("unroll")                                                             \
    for (int i_ = 4; i_ < 8; i_++) {                                              \
        int e_ = tid + i_*256 - 1024;                                             \
        int r_ = e_ >> 3, c_ = e_ & 7;                                            \
        uint32_t off_ = (uint32_t)(r_*128) + (((c_*16) ^ ((r_&7)<<4)));           \
        const __nv_bfloat16* src_ = ((c_<4)? Bh : Bl)                             \
            + (size_t)(n0 + r_)*K + (kc) + (c_&3)*8;                              \
        cpasync16(sB_ + off_, src_);                                              \
    }                                                                             \
    asm volatile("cp.async.commit_group;" ::: "memory");                          \
} while (0)

__global__ __launch_bounds__(256)
void gemm_bf16_mma(const __nv_bfloat16* __restrict__ Ah, const __nv_bfloat16* __restrict__ Al,
                   const __nv_bfloat16* __restrict__ Bh, const __nv_bfloat16* __restrict__ Bl,
                   const float* __restrict__ bias, float* __restrict__ C,
                   int N, int K, int act)
{
    extern __shared__ char smem[];
    const int tid = threadIdx.x, lane = tid & 31, wid = tid >> 5;
    const int m0 = blockIdx.y * BM, n0 = blockIdx.x * BN;
    const int mw = (wid >> 2) * 64, nw = (wid & 3) * 32;
    const int nch = K / BKC;
    uint32_t sbase = smem_u32(smem);

    float acc[4][4][4];
    #pragma unroll
    for (int a = 0; a < 4; a++)
        #pragma unroll
        for (int b = 0; b < 4; b++)
            #pragma unroll
            for (int c = 0; c < 4; c++) acc[a][b][c] = 0.f;

    // precomputed per-lane ldmatrix offsets
    uint32_t arowoff[4], axor[4];
    #pragma unroll
    for (int mt = 0; mt < 4; mt++) {
        int row = mw + mt*16 + (lane & 15);
        arowoff[mt] = (uint32_t)(row * 128);
        axor[mt]    = (uint32_t)((row & 7) << 4);
    }
    uint32_t achunk = (uint32_t)((lane >> 4) << 4);
    uint32_t browoff[2], bxor[2];
    #pragma unroll
    for (int ng = 0; ng < 2; ng++) {
        int row = nw + ng*16 + (lane & 7) + (((lane >> 3) & 1) << 3);
        browoff[ng] = (uint32_t)(row * 128);
        bxor[ng]    = (uint32_t)((row & 7) << 4);
    }
    uint32_t bchunk = (uint32_t)((lane >> 4) << 4);

    // prologue
    #pragma unroll
    for (int s = 0; s < STAGES-1; s++) LOAD_STAGE(s, s*BKC);

    for (int ch = 0; ch < nch; ch++) {
        asm volatile("cp.async.wait_group %0;" :: "n"(STAGES-2) : "memory");
        __syncthreads();
        if (ch + STAGES-1 < nch) LOAD_STAGE((ch + STAGES-1) & 3, (ch + STAGES-1)*BKC);

        uint32_t sA = sbase + (uint32_t)(ch & 3)*STAGE_BYTES;
        uint32_t sB = sA + STAGE_A;
        #pragma unroll
        for (int ks = 0; ks < 2; ks++) {
            uint32_t kb = (uint32_t)(ks*32);
            uint32_t ah[4][4], al[4][4], bh[2][4], bl[2][4];
            #pragma unroll
            for (int mt = 0; mt < 4; mt++) {
                ldsm4(ah[mt][0], ah[mt][1], ah[mt][2], ah[mt][3],
                      sA + arowoff[mt] + ((kb + achunk) ^ axor[mt]));
                ldsm4(al[mt][0], al[mt][1], al[mt][2], al[mt][3],
                      sA + arowoff[mt] + ((64u + kb + achunk) ^ axor[mt]));
            }
            #pragma unroll
            for (int ng = 0; ng < 2; ng++) {
                ldsm4(bh[ng][0], bh[ng][1], bh[ng][2], bh[ng][3],
                      sB + browoff[ng] + ((kb + bchunk) ^ bxor[ng]));
                ldsm4(bl[ng][0], bl[ng][1], bl[ng][2], bl[ng][3],
                      sB + browoff[ng] + ((64u + kb + bchunk) ^ bxor[ng]));
            }
            #pragma unroll
            for (int mt = 0; mt < 4; mt++) {
                #pragma unroll
                for (int nt = 0; nt < 4; nt++) {
                    int ng = nt >> 1, sb = nt & 1;
                    mma16816(acc[mt][nt], ah[mt][0], ah[mt][1], ah[mt][2], ah[mt][3],
                             bh[ng][sb], bh[ng][sb+2]);
                    mma16816(acc[mt][nt], al[mt][0], al[mt][1], al[mt][2], al[mt][3],
                             bh[ng][sb], bh[ng][sb+2]);
                    mma16816(acc[mt][nt], ah[mt][0], ah[mt][1], ah[mt][2], ah[mt][3],
                             bl[ng][sb], bl[ng][sb+2]);
                }
            }
        }
    }

    // epilogue
    const int cm = mw + (lane >> 2);
    const int cn = nw + (lane & 3) * 2;
    #pragma unroll
    for (int mt = 0; mt < 4; mt++) {
        #pragma unroll
        for (int nt = 0; nt < 4; nt++) {
            int row = m0 + cm + mt*16;
            int col = n0 + cn + nt*8;
            float b0 = bias[col], b1 = bias[col+1];
            float v0 = acc[mt][nt][0] + b0, v1 = acc[mt][nt][1] + b1;
            float v2 = acc[mt][nt][2] + b0, v3 = acc[mt][nt][3] + b1;
            if (act) {
                v0 = 0.5f*v0*(1.0f + erff(v0*0.70710678118654752f));
                v1 = 0.5f*v1*(1.0f + erff(v1*0.70710678118654752f));
                v2 = 0.5f*v2*(1.0f + erff(v2*0.70710678118654752f));
                v3 = 0.5f*v3*(1.0f + erff(v3*0.70710678118654752f));
            }
            float2 p0; p0.x = v0; p0.y = v1;
            float2 p1; p1.x = v2; p1.y = v3;
            *(float2*)&C[(size_t)row * N + col]       = p0;
            *(float2*)&C[(size_t)(row + 8) * N + col] = p1;
        }
    }
}

// ---------------- embedding + layernorm ----------------
__global__ void embed_ln_kernel(const int* __restrict__ ids, const int* __restrict__ seg,
                                const float* __restrict__ wemb, const float* __restrict__ pemb,
                                const float* __restrict__ temb, const float* __restrict__ gam,
                                const float* __restrict__ bet, float* __restrict__ X)
{
    int r = blockIdx.x;
    int t = r % TT;
    __shared__ float buf[H];
    __shared__ float red[256];
    int tid = threadIdx.x;
    int id = ids[r], sg = seg[r];
    float lsum = 0.f, lsq = 0.f;
    for (int j = tid; j < H; j += 256) {
        float v = wemb[id*H + j] + pemb[t*H + j] + temb[sg*H + j];
        buf[j] = v; lsum += v; lsq += v*v;
    }
    red[tid] = lsum; __syncthreads();
    for (int s = 128; s > 0; s >>= 1) { if (tid < s) red[tid] += red[tid+s]; __syncthreads(); }
    float mean = red[0] / (float)H; __syncthreads();
    red[tid] = lsq; __syncthreads();
    for (int s = 128; s > 0; s >>= 1) { if (tid < s) red[tid] += red[tid+s]; __syncthreads(); }
    float var = red[0] / (float)H - mean*mean;
    float rstd = rsqrtf(var + 1e-12f);
    for (int j = tid; j < H; j += 256)
        X[r*H + j] = (buf[j] - mean) * rstd * gam[j] + bet[j];
}

// ---------------- residual add + layernorm ----------------
__global__ void add_ln_kernel(const float* __restrict__ X, const float* __restrict__ D,
                              const float* __restrict__ gam, const float* __restrict__ bet,
                              float* __restrict__ Y)
{
    int r = blockIdx.x;
    __shared__ float buf[H];
    __shared__ float red[256];
    int tid = threadIdx.x;
    float lsum = 0.f, lsq = 0.f;
    for (int j = tid; j < H; j += 256) {
        float v = X[r*H + j] + D[r*H + j];
        buf[j] = v; lsum += v; lsq += v*v;
    }
    red[tid] = lsum; __syncthreads();
    for (int s = 128; s > 0; s >>= 1) { if (tid < s) red[tid] += red[tid+s]; __syncthreads(); }
    float mean = red[0] / (float)H; __syncthreads();
    red[tid] = lsq; __syncthreads();
    for (int s = 128; s > 0; s >>= 1) { if (tid < s) red[tid] += red[tid+s]; __syncthreads(); }
    float var = red[0] / (float)H - mean*mean;
    float rstd = rsqrtf(var + 1e-12f);
    for (int j = tid; j < H; j += 256)
        Y[r*H + j] = (buf[j] - mean) * rstd * gam[j] + bet[j];
}

// ---------------- fused attention (per b,h block; K,V in smem) ----------------
#define ATT_LD 65
#define ATT_SMEM_FLOATS (2*TT*ATT_LD + DH + TT + TT)
__global__ void attention_kernel(const float* __restrict__ QKV,
                                 const int* __restrict__ mask,
                                 float* __restrict__ O)
{
    extern __shared__ float sm[];
    float* Ks    = sm;
    float* Vs    = Ks + TT*ATT_LD;
    float* qrow  = Vs + TT*ATT_LD;
    float* probs = qrow + DH;
    float* red   = probs + TT;

    int h = blockIdx.x, b = blockIdx.y;
    int tid = threadIdx.x;
    const float* Kb = QKV + (size_t)(b*TT)*QKVN + H   + h*DH;
    const float* Vb = QKV + (size_t)(b*TT)*QKVN + 2*H + h*DH;
    for (int idx = tid; idx < TT*DH; idx += 256) {
        int s = idx >> 6, d = idx & 63;
        Ks[s*ATT_LD + d] = Kb[(size_t)s*QKVN + d];
        Vs[s*ATT_LD + d] = Vb[(size_t)s*QKVN + d];
    }
    float mbias = (mask[b*TT + tid] != 0) ? 0.f : -10000.f;
    __syncthreads();

    const float scale = 0.125f;
    int dd = tid & 63, part = tid >> 6;

    for (int t = 0; t < TT; t++) {
        if (tid < DH) qrow[tid] = QKV[(size_t)(b*TT + t)*QKVN + h*DH + tid];
        __syncthreads();
        float dot = 0.f;
        #pragma unroll 16
        for (int d = 0; d < DH; d++) dot += qrow[d] * Ks[tid*ATT_LD + d];
        float sc = dot * scale + mbias;
        red[tid] = sc; __syncthreads();
        for (int s = 128; s > 0; s >>= 1) {
            if (tid < s) { float o = red[tid+s]; if (o > red[tid]) red[tid] = o; }
            __syncthreads();
        }
        float mx = red[0]; __syncthreads();
        float p = expf(sc - mx);
        probs[tid] = p;
        red[tid] = p; __syncthreads();
        for (int s = 128; s > 0; s >>= 1) { if (tid < s) red[tid] += red[tid+s]; __syncthreads(); }
        float inv = 1.f / red[0]; __syncthreads();
        float acc = 0.f;
        int sBeg = part * 64;
        #pragma unroll 16
        for (int ss = 0; ss < 64; ss++)
            acc += probs[sBeg + ss] * Vs[(sBeg + ss)*ATT_LD + dd];
        red[tid] = acc; __syncthreads();
        if (tid < DH) {
            float o = (red[tid] + red[tid+64] + red[tid+128] + red[tid+192]) * inv;
            O[(size_t)(b*TT + t)*H + h*DH + tid] = o;
        }
        __syncthreads();
    }
}

// ---------------- head GEMM (N=35) ----------------
__global__ void head_gemm(const float* __restrict__ X, const float* __restrict__ W,
                          const float* __restrict__ bias, float* __restrict__ Lg)
{
    int r = blockIdx.x;
    __shared__ float xs[H];
    for (int j = threadIdx.x; j < H; j += blockDim.x) xs[j] = X[(size_t)r*H + j];
    __syncthreads();
    if (threadIdx.x < KK) {
        int k = threadIdx.x;
        float s = bias[k];
        for (int j = 0; j < H; j++) s += xs[j] * W[j*KK + k];
        Lg[r*KK + k] = s;
    }
}

// ---------------- CRF forward + gold score ----------------
__global__ void crf_forward_kernel(const float* __restrict__ logits,
                                   const int* __restrict__ mask,
                                   const int* __restrict__ labels,
                                   const float* __restrict__ trans,
                                   float* __restrict__ fwd, float* __restrict__ gold)
{
    int b = blockIdx.x;
    __shared__ float tr[KK*KK];
    __shared__ float alpha[KK];
    int tid = threadIdx.x;
    for (int i = tid; i < KK*KK; i += 64) tr[i] = trans[i];
    __syncthreads();
    int j = tid;
    if (j < KK) alpha[j] = tr[START_TAG*KK + j] + logits[(size_t)(b*TT)*KK + j];
    __syncthreads();
    for (int t = 1; t < TT; t++) {
        float nv = 0.f;
        if (j < KK) {
            float mxv = -1e30f;
            for (int i = 0; i < KK; i++) { float v = alpha[i] + tr[i*KK + j]; if (v > mxv) mxv = v; }
            float s = 0.f;
            for (int i = 0; i < KK; i++) s += expf(alpha[i] + tr[i*KK + j] - mxv);
            nv = mxv + logf(s) + logits[(size_t)(b*TT + t)*KK + j];
        }
        int keep = (mask[b*TT + t] != 0);
        __syncthreads();
        if (j < KK && keep) alpha[j] = nv;
        __syncthreads();
    }
    if (j == 0) {
        float mxv = -1e30f;
        for (int i = 0; i < KK; i++) { float v = alpha[i] + tr[i*KK + END_TAG]; if (v > mxv) mxv = v; }
        float s = 0.f;
        for (int i = 0; i < KK; i++) s += expf(alpha[i] + tr[i*KK + END_TAG] - mxv);
        fwd[b] = mxv + logf(s);

        int tag0 = labels[b*TT + 0];
        float sc = tr[START_TAG*KK + tag0] + logits[(size_t)(b*TT)*KK + tag0];
        int prev = tag0;
        int lengths = 0;
        for (int t = 0; t < TT; t++) lengths += (mask[b*TT + t] != 0);
        for (int t = 1; t < TT; t++) {
            int tg = labels[b*TT + t];
            float mt = (mask[b*TT + t] != 0) ? 1.f : 0.f;
            sc += (tr[prev*KK + tg] + logits[(size_t)(b*TT + t)*KK + tg]) * mt;
            prev = tg;
        }
        int li = lengths - 1; if (li < 0) li = 0; if (li > TT-1) li = TT-1;
        int last_tag = labels[b*TT + li];
        sc += tr[last_tag*KK + END_TAG];
        gold[b] = sc;
    }
}

__global__ void loss_kernel(const float* __restrict__ fwd, const float* __restrict__ gold,
                            float* __restrict__ out)
{
    if (threadIdx.x == 0 && blockIdx.x == 0) {
        float s = 0.f;
        for (int b = 0; b < BB; b++) s += fwd[b] - gold[b];
        out[0] = s / (float)BB;
    }
}

// ---------------- Viterbi ----------------
__global__ void viterbi_kernel(const float* __restrict__ logits,
                               const int* __restrict__ mask,
                               const float* __restrict__ trans,
                               int* __restrict__ bps,
                               float* __restrict__ out)
{
    int b = blockIdx.x;
    __shared__ float tr[KK*KK];
    __shared__ float alpha[KK];
    int tid = threadIdx.x;
    for (int i = tid; i < KK*KK; i += 64) tr[i] = trans[i];
    __syncthreads();
    int j = tid;
    if (j < KK) alpha[j] = tr[START_TAG*KK + j] + logits[(size_t)(b*TT)*KK + j];
    __syncthreads();
    for (int t = 1; t < TT; t++) {
        float vmax = -1e30f; int bp = 0;
        if (j < KK) {
            for (int i = 0; i < KK; i++) {
                float v = alpha[i] + tr[i*KK + j];
                if (v > vmax) { vmax = v; bp = i; }
            }
            vmax += logits[(size_t)(b*TT + t)*KK + j];
        }
        int keep = (mask[b*TT + t] != 0);
        __syncthreads();
        if (j < KK) {
            if (keep) alpha[j] = vmax;
            bps[((t-1)*BB + b)*KK + j] = keep ? bp : j;
        }
        __syncthreads();
    }
    if (j == 0) {
        float best = -1e30f; int cur = 0;
        for (int i = 0; i < KK; i++) {
            float v = alpha[i] + tr[i*KK + END_TAG];
            if (v > best) { best = v; cur = i; }
        }
        out[1 + b*TT + (TT-1)] = (float)cur;
        for (int tt = TT-2; tt >= 0; tt--) {
            cur = bps[(tt*BB + b)*KK + cur];
            out[1 + b*TT + tt] = (float)cur;
        }
    }
}

// ---------------- host orchestration ----------------
extern "C" void kernel_launch(void* const* d_in, const int* in_sizes, int n_in,
                              void* d_out, int out_size)
{
    const int*   ids  = (const int*)  d_in[0];
    const int*   msk  = (const int*)  d_in[1];
    const int*   seg  = (const int*)  d_in[2];
    const int*   lab  = (const int*)  d_in[3];
    const float* wemb = (const float*)d_in[4];
    const float* pemb = (const float*)d_in[5];
    const float* temb = (const float*)d_in[6];
    const float* eg   = (const float*)d_in[7];
    const float* eb   = (const float*)d_in[8];
    const float* Wq   = (const float*)d_in[9];
    const float* bq   = (const float*)d_in[10];
    const float* Wk   = (const float*)d_in[11];
    const float* bk   = (const float*)d_in[12];
    const float* Wv   = (const float*)d_in[13];
    const float* bv   = (const float*)d_in[14];
    const float* Wo   = (const float*)d_in[15];
    const float* bo   = (const float*)d_in[16];
    const float* ln1g = (const float*)d_in[17];
    const float* ln1b = (const float*)d_in[18];
    const float* W1   = (const float*)d_in[19];
    const float* b1   = (const float*)d_in[20];
    const float* W2   = (const float*)d_in[21];
    const float* b2   = (const float*)d_in[22];
    const float* ln2g = (const float*)d_in[23];
    const float* ln2b = (const float*)d_in[24];
    const float* Wh   = (const float*)d_in[25];
    const float* bh   = (const float*)d_in[26];
    const float* trn  = (const float*)d_in[27];
    float* out = (float*)d_out;

    float *px, *pctx, *ptmp, *pff, *pqkv, *plog, *pfwd, *pgold, *pbqkv;
    int* pbp;
    __nv_bfloat16 *pah, *pal, *pwqh, *pwql, *pwoh, *pwol, *pw1h, *pw1l, *pw2h, *pw2l;
    cudaGetSymbolAddress((void**)&px,    g_x);
    cudaGetSymbolAddress((void**)&pctx,  g_ctx);
    cudaGetSymbolAddress((void**)&ptmp,  g_tmp);
    cudaGetSymbolAddress((void**)&pff,   g_ff);
    cudaGetSymbolAddress((void**)&pqkv,  g_qkv);
    cudaGetSymbolAddress((void**)&plog,  g_logits);
    cudaGetSymbolAddress((void**)&pfwd,  g_fwd);
    cudaGetSymbolAddress((void**)&pgold, g_gold);
    cudaGetSymbolAddress((void**)&pbp,   g_bp);
    cudaGetSymbolAddress((void**)&pbqkv, g_bqkv);
    cudaGetSymbolAddress((void**)&pah,   g_ah);
    cudaGetSymbolAddress((void**)&pal,   g_al);
    cudaGetSymbolAddress((void**)&pwqh,  g_wqkv_h);
    cudaGetSymbolAddress((void**)&pwql,  g_wqkv_l);
    cudaGetSymbolAddress((void**)&pwoh,  g_wo_h);
    cudaGetSymbolAddress((void**)&pwol,  g_wo_l);
    cudaGetSymbolAddress((void**)&pw1h,  g_w1_h);
    cudaGetSymbolAddress((void**)&pw1l,  g_w1_l);
    cudaGetSymbolAddress((void**)&pw2h,  g_w2_h);
    cudaGetSymbolAddress((void**)&pw2l,  g_w2_l);

    const size_t att_smem = ATT_SMEM_FLOATS * sizeof(float);
    cudaFuncSetAttribute(attention_kernel,
                         cudaFuncAttributeMaxDynamicSharedMemorySize, (int)att_smem);
    cudaFuncSetAttribute(gemm_bf16_mma,
                         cudaFuncAttributeMaxDynamicSharedMemorySize, GEMM_SMEM);

    // ---- weight preprocessing (transpose + bf16 hi/lo split) ----
    dim3 tb(32, 8);
    pack_bias<<<LNUM, 256>>>(bq, bk, bv, pbqkv);
    wsplit<<<dim3(H/32, H/32, LNUM), tb>>>(Wq, pwqh,                pwql,                H, H,
                                           (size_t)H*H, (size_t)QKVN*H);
    wsplit<<<dim3(H/32, H/32, LNUM), tb>>>(Wk, pwqh + (size_t)H*H,  pwql + (size_t)H*H,  H, H,
                                           (size_t)H*H, (size_t)QKVN*H);
    wsplit<<<dim3(H/32, H/32, LNUM), tb>>>(Wv, pwqh + (size_t)2*H*H, pwql + (size_t)2*H*H, H, H,
                                           (size_t)H*H, (size_t)QKVN*H);
    wsplit<<<dim3(H/32, H/32, LNUM), tb>>>(Wo, pwoh, pwol, H, H, (size_t)H*H, (size_t)H*H);
    wsplit<<<dim3(H/32, FF/32, LNUM), tb>>>(W1, pw1h, pw1l, H, FF, (size_t)H*FF, (size_t)FF*H);
    wsplit<<<dim3(FF/32, H/32, LNUM), tb>>>(W2, pw2h, pw2l, FF, H, (size_t)FF*H, (size_t)H*FF);

    // ---- embedding ----
    embed_ln_kernel<<<ROWS, 256>>>(ids, seg, wemb, pemb, temb, eg, eb, px);

    for (int l = 0; l < LNUM; l++) {
        // QKV (fused, N=2304)
        asplit<<<(ROWS*H)/1024, 256>>>(px, pah, pal, (ROWS*H)/4);
        gemm_bf16_mma<<<dim3(QKVN/BN, ROWS/BM), 256, GEMM_SMEM>>>(
            pah, pal, pwqh + (size_t)l*QKVN*H, pwql + (size_t)l*QKVN*H,
            pbqkv + (size_t)l*QKVN, pqkv, QKVN, H, 0);

        attention_kernel<<<dim3(NH, BB), 256, att_smem>>>(pqkv, msk, pctx);

        // output proj
        asplit<<<(ROWS*H)/1024, 256>>>(pctx, pah, pal, (ROWS*H)/4);
        gemm_bf16_mma<<<dim3(H/BN, ROWS/BM), 256, GEMM_SMEM>>>(
            pah, pal, pwoh + (size_t)l*H*H, pwol + (size_t)l*H*H,
            bo + (size_t)l*H, ptmp, H, H, 0);
        add_ln_kernel<<<ROWS, 256>>>(px, ptmp, ln1g + (size_t)l*H, ln1b + (size_t)l*H, px);

        // FF1 (+GELU)
        asplit<<<(ROWS*H)/1024, 256>>>(px, pah, pal, (ROWS*H)/4);
        gemm_bf16_mma<<<dim3(FF/BN, ROWS/BM), 256, GEMM_SMEM>>>(
            pah, pal, pw1h + (size_t)l*FF*H, pw1l + (size_t)l*FF*H,
            b1 + (size_t)l*FF, pff, FF, H, 1);

        // FF2
        asplit<<<(ROWS*FF)/1024, 256>>>(pff, pah, pal, (ROWS*FF)/4);
        gemm_bf16_mma<<<dim3(H/BN, ROWS/BM), 256, GEMM_SMEM>>>(
            pah, pal, pw2h + (size_t)l*H*FF, pw2l + (size_t)l*H*FF,
            b2 + (size_t)l*H, ptmp, H, FF, 0);
        add_ln_kernel<<<ROWS, 256>>>(px, ptmp, ln2g + (size_t)l*H, ln2b + (size_t)l*H, px);
    }

    head_gemm<<<ROWS, 128>>>(px, Wh, bh, plog);
    crf_forward_kernel<<<BB, 64>>>(plog, msk, lab, trn, pfwd, pgold);
    loss_kernel<<<1, 32>>>(pfwd, pgold, out);
    viterbi_kernel<<<BB, 64>>>(plog, msk, trn, pbp, out);
}

// round 6
// speedup vs baseline: 1.9518x; 1.1397x over previous
#include <cuda_runtime.h>
#include <cuda_bf16.h>
#include <math.h>
#include <stdint.h>

// ---------------- problem constants ----------------
#define LNUM 12
#define H    768
#define NH   12
#define DH   64
#define FF   3072
#define TT   256
#define BB   32
#define KK   35
#define START_TAG 33
#define END_TAG   34
#define ROWS (BB*TT)            // 8192
#define QKVN 2304               // fused q|k|v output width

// ---------------- device scratch (allocation-free) ----------------
__device__ float g_x   [ROWS*H];
__device__ float g_tmp [ROWS*H];
__device__ float g_qkv [ROWS*QKVN];
__device__ float g_logits[ROWS*KK];
__device__ float g_fwd [BB];
__device__ float g_gold[BB];
__device__ int   g_bp  [(TT-1)*BB*KK];

__device__ __nv_bfloat16 g_xh[ROWS*H],  g_xl[ROWS*H];     // x split
__device__ __nv_bfloat16 g_ch[ROWS*H],  g_cl[ROWS*H];     // ctx split
__device__ __nv_bfloat16 g_fh[ROWS*FF], g_fl[ROWS*FF];    // ff split
__device__ __nv_bfloat16 g_wqkv_h[LNUM*QKVN*H], g_wqkv_l[LNUM*QKVN*H];
__device__ __nv_bfloat16 g_wo_h[LNUM*H*H],      g_wo_l[LNUM*H*H];
__device__ __nv_bfloat16 g_w1_h[LNUM*FF*H],     g_w1_l[LNUM*FF*H];
__device__ __nv_bfloat16 g_w2_h[LNUM*H*FF],     g_w2_l[LNUM*H*FF];
__device__ float g_bqkv[LNUM*QKVN];

// ---------------- PTX helpers (sm_80-compatible only) ----------------
__device__ __forceinline__ uint32_t smem_u32(const void* p) {
    uint32_t a;
    asm("{ .reg .u64 t; cvta.to.shared.u64 t, %1; cvt.u32.u64 %0, t; }" : "=r"(a) : "l"(p));
    return a;
}
__device__ __forceinline__ void cpasync16(uint32_t s, const void* g) {
    asm volatile("cp.async.cg.shared.global [%0], [%1], 16;" :: "r"(s), "l"(g));
}
__device__ __forceinline__ void ldsm4(uint32_t& r0, uint32_t& r1, uint32_t& r2, uint32_t& r3,
                                      uint32_t addr) {
    asm volatile("ldmatrix.sync.aligned.m8n8.x4.shared.b16 {%0,%1,%2,%3}, [%4];"
                 : "=r"(r0), "=r"(r1), "=r"(r2), "=r"(r3) : "r"(addr));
}
__device__ __forceinline__ void mma16816(float* d, uint32_t a0, uint32_t a1, uint32_t a2,
                                         uint32_t a3, uint32_t b0, uint32_t b1) {
    asm volatile(
        "mma.sync.aligned.m16n8k16.row.col.f32.bf16.bf16.f32 "
        "{%0,%1,%2,%3}, {%4,%5,%6,%7}, {%8,%9}, {%0,%1,%2,%3};"
        : "+f"(d[0]), "+f"(d[1]), "+f"(d[2]), "+f"(d[3])
        : "r"(a0), "r"(a1), "r"(a2), "r"(a3), "r"(b0), "r"(b1));
}
__device__ __forceinline__ void split2(float v, __nv_bfloat16& h, __nv_bfloat16& l) {
    h = __float2bfloat16(v);
    l = __float2bfloat16(v - __bfloat162float(h));
}

// transpose + split: W[K,N] fp32 (row-major) -> out[N,K] bf16 hi/lo
__global__ void wsplit(const float* __restrict__ W,
                       __nv_bfloat16* __restrict__ hi, __nv_bfloat16* __restrict__ lo,
                       int K, int N, size_t w_lstride, size_t o_lstride)
{
    int l = blockIdx.z;
    const float* Wl = W + (size_t)l * w_lstride;
    __shared__ float t[32][33];
    int k0 = blockIdx.x * 32, n0 = blockIdx.y * 32;
    for (int i = threadIdx.y; i < 32; i += 8)
        t[i][threadIdx.x] = Wl[(size_t)(k0 + i) * N + n0 + threadIdx.x];
    __syncthreads();
    for (int i = threadIdx.y; i < 32; i += 8) {
        int n = n0 + i, k = k0 + threadIdx.x;
        float v = t[threadIdx.x][i];
        __nv_bfloat16 h, lw; split2(v, h, lw);
        size_t o = (size_t)l * o_lstride + (size_t)n * K + k;
        hi[o] = h; lo[o] = lw;
    }
}

__global__ void pack_bias(const float* __restrict__ bq, const float* __restrict__ bk,
                          const float* __restrict__ bv, float* __restrict__ bqkv)
{
    int l = blockIdx.x;
    for (int j = threadIdx.x; j < H; j += blockDim.x) {
        bqkv[l*QKVN + j]        = bq[l*H + j];
        bqkv[l*QKVN + H + j]    = bk[l*H + j];
        bqkv[l*QKVN + 2*H + j]  = bv[l*H + j];
    }
}

// ---------------- mma.sync split-bf16 GEMM ----------------
// C[M,N] = (Ah+Al)[M,K] @ (Bh+Bl)[N,K]^T + bias   (lo*lo dropped)
// tile 128x128x32 per CTA, 8 warps (2x4), warp 64x32, 4-stage cp.async.
// flags: 1=gelu, 2=write fp32 C, 4=write split hi/lo
#define BM 128
#define BN 128
#define BKC 32
#define STAGES 4
#define STAGE_A (BM*128)                 // 16384 B (hi|lo packed per row)
#define STAGE_BYTES (STAGE_A + BN*128)   // 32768
#define GEMM_SMEM (STAGES*STAGE_BYTES)   // 131072

#define LOAD_STAGE(st, kc) do {                                                   \
    uint32_t sA_ = sbase + (uint32_t)(st)*STAGE_BYTES;                            \
    uint32_t sB_ = sA_ + STAGE_A;                                                 \
    _Pragma("unroll")                                                             \
    for (int i_ = 0; i_ < 4; i_++) {                                              \
        int e_ = tid + i_*256;                                                    \
        int r_ = e_ >> 3, c_ = e_ & 7;                                            \
        uint32_t off_ = (uint32_t)(r_*128) + (((c_*16) ^ ((r_&7)<<4)));           \
        const __nv_bfloat16* src_ = ((c_<4)? Ah : Al)                             \
            + (size_t)(m0 + r_)*K + (kc) + (c_&3)*8;                              \
        cpasync16(sA_ + off_, src_);                                              \
    }                                                                             \
    _Pragma("unroll")                                                             \
    for (int i_ = 4; i_ < 8; i_++) {                                              \
        int e_ = tid + i_*256 - 1024;                                             \
        int r_ = e_ >> 3, c_ = e_ & 7;                                            \
        uint32_t off_ = (uint32_t)(r_*128) + (((c_*16) ^ ((r_&7)<<4)));           \
        const __nv_bfloat16* src_ = ((c_<4)? Bh : Bl)                             \
            + (size_t)(n0 + r_)*K + (kc) + (c_&3)*8;                              \
        cpasync16(sB_ + off_, src_);                                              \
    }                                                                             \
    asm volatile("cp.async.commit_group;" ::: "memory");                          \
} while (0)

__global__ __launch_bounds__(256)
void gemm_bf16_mma(const __nv_bfloat16* __restrict__ Ah, const __nv_bfloat16* __restrict__ Al,
                   const __nv_bfloat16* __restrict__ Bh, const __nv_bfloat16* __restrict__ Bl,
                   const float* __restrict__ bias, float* __restrict__ C,
                   __nv_bfloat16* __restrict__ Chi, __nv_bfloat16* __restrict__ Clo,
                   int N, int K, int flags)
{
    extern __shared__ char smem[];
    const int tid = threadIdx.x, lane = tid & 31, wid = tid >> 5;
    const int m0 = blockIdx.y * BM, n0 = blockIdx.x * BN;
    const int mw = (wid >> 2) * 64, nw = (wid & 3) * 32;
    const int nch = K / BKC;
    uint32_t sbase = smem_u32(smem);

    float acc[4][4][4];
    #pragma unroll
    for (int a = 0; a < 4; a++)
        #pragma unroll
        for (int b = 0; b < 4; b++)
            #pragma unroll
            for (int c = 0; c < 4; c++) acc[a][b][c] = 0.f;

    // precomputed per-lane ldmatrix offsets
    uint32_t arowoff[4], axor[4];
    #pragma unroll
    for (int mt = 0; mt < 4; mt++) {
        int row = mw + mt*16 + (lane & 15);
        arowoff[mt] = (uint32_t)(row * 128);
        axor[mt]    = (uint32_t)((row & 7) << 4);
    }
    uint32_t achunk = (uint32_t)((lane >> 4) << 4);
    uint32_t browoff[2], bxor[2];
    #pragma unroll
    for (int ng = 0; ng < 2; ng++) {
        int row = nw + ng*16 + (lane & 7) + (((lane >> 3) & 1) << 3);
        browoff[ng] = (uint32_t)(row * 128);
        bxor[ng]    = (uint32_t)((row & 7) << 4);
    }
    uint32_t bchunk = (uint32_t)((lane >> 4) << 4);

    // prologue
    #pragma unroll
    for (int s = 0; s < STAGES-1; s++) LOAD_STAGE(s, s*BKC);

    for (int ch = 0; ch < nch; ch++) {
        asm volatile("cp.async.wait_group %0;" :: "n"(STAGES-2) : "memory");
        __syncthreads();
        if (ch + STAGES-1 < nch) LOAD_STAGE((ch + STAGES-1) & 3, (ch + STAGES-1)*BKC);

        uint32_t sA = sbase + (uint32_t)(ch & 3)*STAGE_BYTES;
        uint32_t sB = sA + STAGE_A;
        #pragma unroll
        for (int ks = 0; ks < 2; ks++) {
            uint32_t kb = (uint32_t)(ks*32);
            uint32_t ah[4][4], al[4][4], bh[2][4], bl[2][4];
            #pragma unroll
            for (int mt = 0; mt < 4; mt++) {
                ldsm4(ah[mt][0], ah[mt][1], ah[mt][2], ah[mt][3],
                      sA + arowoff[mt] + ((kb + achunk) ^ axor[mt]));
                ldsm4(al[mt][0], al[mt][1], al[mt][2], al[mt][3],
                      sA + arowoff[mt] + ((64u + kb + achunk) ^ axor[mt]));
            }
            #pragma unroll
            for (int ng = 0; ng < 2; ng++) {
                ldsm4(bh[ng][0], bh[ng][1], bh[ng][2], bh[ng][3],
                      sB + browoff[ng] + ((kb + bchunk) ^ bxor[ng]));
                ldsm4(bl[ng][0], bl[ng][1], bl[ng][2], bl[ng][3],
                      sB + browoff[ng] + ((64u + kb + bchunk) ^ bxor[ng]));
            }
            // product-major ordering: 16 independent MMAs per pass so no
            // back-to-back dependent accumulator writes.
            #pragma unroll
            for (int mt = 0; mt < 4; mt++)
                #pragma unroll
                for (int nt = 0; nt < 4; nt++) {
                    int ng = nt >> 1, sb = nt & 1;
                    mma16816(acc[mt][nt], ah[mt][0], ah[mt][1], ah[mt][2], ah[mt][3],
                             bh[ng][sb], bh[ng][sb+2]);
                }
            #pragma unroll
            for (int mt = 0; mt < 4; mt++)
                #pragma unroll
                for (int nt = 0; nt < 4; nt++) {
                    int ng = nt >> 1, sb = nt & 1;
                    mma16816(acc[mt][nt], al[mt][0], al[mt][1], al[mt][2], al[mt][3],
                             bh[ng][sb], bh[ng][sb+2]);
                }
            #pragma unroll
            for (int mt = 0; mt < 4; mt++)
                #pragma unroll
                for (int nt = 0; nt < 4; nt++) {
                    int ng = nt >> 1, sb = nt & 1;
                    mma16816(acc[mt][nt], ah[mt][0], ah[mt][1], ah[mt][2], ah[mt][3],
                             bl[ng][sb], bl[ng][sb+2]);
                }
        }
    }

    // epilogue
    const int cm = mw + (lane >> 2);
    const int cn = nw + (lane & 3) * 2;
    #pragma unroll
    for (int mt = 0; mt < 4; mt++) {
        #pragma unroll
        for (int nt = 0; nt < 4; nt++) {
            int row = m0 + cm + mt*16;
            int col = n0 + cn + nt*8;
            float b0 = bias[col], b1 = bias[col+1];
            float v0 = acc[mt][nt][0] + b0, v1 = acc[mt][nt][1] + b1;
            float v2 = acc[mt][nt][2] + b0, v3 = acc[mt][nt][3] + b1;
            if (flags & 1) {
                v0 = 0.5f*v0*(1.0f + erff(v0*0.70710678118654752f));
                v1 = 0.5f*v1*(1.0f + erff(v1*0.70710678118654752f));
                v2 = 0.5f*v2*(1.0f + erff(v2*0.70710678118654752f));
                v3 = 0.5f*v3*(1.0f + erff(v3*0.70710678118654752f));
            }
            size_t o0 = (size_t)row * N + col;
            size_t o1 = (size_t)(row + 8) * N + col;
            if (flags & 2) {
                float2 p0; p0.x = v0; p0.y = v1;
                float2 p1; p1.x = v2; p1.y = v3;
                *(float2*)&C[o0] = p0;
                *(float2*)&C[o1] = p1;
            }
            if (flags & 4) {
                __nv_bfloat16 h0, l0, h1, l1, h2, l2, h3, l3;
                split2(v0, h0, l0); split2(v1, h1, l1);
                split2(v2, h2, l2); split2(v3, h3, l3);
                uint32_t hp0 = (uint32_t)__bfloat16_as_ushort(h0) | ((uint32_t)__bfloat16_as_ushort(h1) << 16);
                uint32_t hp1 = (uint32_t)__bfloat16_as_ushort(h2) | ((uint32_t)__bfloat16_as_ushort(h3) << 16);
                uint32_t lp0 = (uint32_t)__bfloat16_as_ushort(l0) | ((uint32_t)__bfloat16_as_ushort(l1) << 16);
                uint32_t lp1 = (uint32_t)__bfloat16_as_ushort(l2) | ((uint32_t)__bfloat16_as_ushort(l3) << 16);
                *(uint32_t*)&Chi[o0] = hp0;
                *(uint32_t*)&Chi[o1] = hp1;
                *(uint32_t*)&Clo[o0] = lp0;
                *(uint32_t*)&Clo[o1] = lp1;
            }
        }
    }
}

// ---------------- embedding + layernorm (+ split) ----------------
__global__ void embed_ln_kernel(const int* __restrict__ ids, const int* __restrict__ seg,
                                const float* __restrict__ wemb, const float* __restrict__ pemb,
                                const float* __restrict__ temb, const float* __restrict__ gam,
                                const float* __restrict__ bet, float* __restrict__ X,
                                __nv_bfloat16* __restrict__ Xh, __nv_bfloat16* __restrict__ Xl)
{
    int r = blockIdx.x;
    int t = r % TT;
    __shared__ float buf[H];
    __shared__ float red[256];
    int tid = threadIdx.x;
    int id = ids[r], sg = seg[r];
    float lsum = 0.f, lsq = 0.f;
    for (int j = tid; j < H; j += 256) {
        float v = wemb[id*H + j] + pemb[t*H + j] + temb[sg*H + j];
        buf[j] = v; lsum += v; lsq += v*v;
    }
    red[tid] = lsum; __syncthreads();
    for (int s = 128; s > 0; s >>= 1) { if (tid < s) red[tid] += red[tid+s]; __syncthreads(); }
    float mean = red[0] / (float)H; __syncthreads();
    red[tid] = lsq; __syncthreads();
    for (int s = 128; s > 0; s >>= 1) { if (tid < s) red[tid] += red[tid+s]; __syncthreads(); }
    float var = red[0] / (float)H - mean*mean;
    float rstd = rsqrtf(var + 1e-12f);
    for (int j = tid; j < H; j += 256) {
        float y = (buf[j] - mean) * rstd * gam[j] + bet[j];
        X[r*H + j] = y;
        __nv_bfloat16 h, l; split2(y, h, l);
        Xh[r*H + j] = h; Xl[r*H + j] = l;
    }
}

// ---------------- residual add + layernorm (+ split) ----------------
__global__ void add_ln_kernel(const float* __restrict__ X, const float* __restrict__ D,
                              const float* __restrict__ gam, const float* __restrict__ bet,
                              float* __restrict__ Y,
                              __nv_bfloat16* __restrict__ Yh, __nv_bfloat16* __restrict__ Yl)
{
    int r = blockIdx.x;
    __shared__ float buf[H];
    __shared__ float red[256];
    int tid = threadIdx.x;
    float lsum = 0.f, lsq = 0.f;
    for (int j = tid; j < H; j += 256) {
        float v = X[r*H + j] + D[r*H + j];
        buf[j] = v; lsum += v; lsq += v*v;
    }
    red[tid] = lsum; __syncthreads();
    for (int s = 128; s > 0; s >>= 1) { if (tid < s) red[tid] += red[tid+s]; __syncthreads(); }
    float mean = red[0] / (float)H; __syncthreads();
    red[tid] = lsq; __syncthreads();
    for (int s = 128; s > 0; s >>= 1) { if (tid < s) red[tid] += red[tid+s]; __syncthreads(); }
    float var = red[0] / (float)H - mean*mean;
    float rstd = rsqrtf(var + 1e-12f);
    for (int j = tid; j < H; j += 256) {
        float y = (buf[j] - mean) * rstd * gam[j] + bet[j];
        Y[r*H + j] = y;
        __nv_bfloat16 h, l; split2(y, h, l);
        Yh[r*H + j] = h; Yl[r*H + j] = l;
    }
}

// ---------------- fused attention (per b,h block; K,V in smem) ----------------
// outputs split bf16 directly; warp-shuffle reductions (4 syncs per step)
#define ATT_LD 65
#define ATT_SMEM_FLOATS (2*TT*ATT_LD + DH + TT + TT + 16)
__global__ void attention_kernel(const float* __restrict__ QKV,
                                 const int* __restrict__ mask,
                                 __nv_bfloat16* __restrict__ Oh,
                                 __nv_bfloat16* __restrict__ Ol)
{
    extern __shared__ float sm[];
    float* Ks    = sm;
    float* Vs    = Ks + TT*ATT_LD;
    float* qrow  = Vs + TT*ATT_LD;
    float* probs = qrow + DH;
    float* red   = probs + TT;
    float* wred  = red + TT;          // [0..7]=max, [8..15]=sum

    int h = blockIdx.x, b = blockIdx.y;
    int tid = threadIdx.x, lane = tid & 31, warp = tid >> 5;
    const float* Kb = QKV + (size_t)(b*TT)*QKVN + H   + h*DH;
    const float* Vb = QKV + (size_t)(b*TT)*QKVN + 2*H + h*DH;
    for (int idx = tid; idx < TT*DH; idx += 256) {
        int s = idx >> 6, d = idx & 63;
        Ks[s*ATT_LD + d] = Kb[(size_t)s*QKVN + d];
        Vs[s*ATT_LD + d] = Vb[(size_t)s*QKVN + d];
    }
    float mbias = (mask[b*TT + tid] != 0) ? 0.f : -10000.f;
    __syncthreads();

    const float scale = 0.125f;
    int dd = tid & 63, part = tid >> 6;

    for (int t = 0; t < TT; t++) {
        if (tid < DH) qrow[tid] = QKV[(size_t)(b*TT + t)*QKVN + h*DH + tid];
        __syncthreads();                                    // S1
        float dot = 0.f;
        #pragma unroll 16
        for (int d = 0; d < DH; d++) dot += qrow[d] * Ks[tid*ATT_LD + d];
        float sc = dot * scale + mbias;

        float wm = sc;
        #pragma unroll
        for (int off = 16; off > 0; off >>= 1)
            wm = fmaxf(wm, __shfl_xor_sync(0xFFFFFFFFu, wm, off));
        if (lane == 0) wred[warp] = wm;
        __syncthreads();                                    // S2
        float mx = wred[0];
        #pragma unroll
        for (int w = 1; w < 8; w++) mx = fmaxf(mx, wred[w]);

        float p = expf(sc - mx);
        probs[tid] = p;
        float ws = p;
        #pragma unroll
        for (int off = 16; off > 0; off >>= 1)
            ws += __shfl_xor_sync(0xFFFFFFFFu, ws, off);
        if (lane == 0) wred[8 + warp] = ws;
        __syncthreads();                                    // S3
        float sum = wred[8];
        #pragma unroll
        for (int w = 9; w < 16; w++) sum += wred[w];
        float inv = 1.f / sum;

        float acc = 0.f;
        int sBeg = part * 64;
        #pragma unroll 16
        for (int ss = 0; ss < 64; ss++)
            acc += probs[sBeg + ss] * Vs[(sBeg + ss)*ATT_LD + dd];
        red[tid] = acc;
        __syncthreads();                                    // S4
        if (tid < DH) {
            float o = (red[tid] + red[tid+64] + red[tid+128] + red[tid+192]) * inv;
            __nv_bfloat16 hh, ll; split2(o, hh, ll);
            size_t oo = (size_t)(b*TT + t)*H + h*DH + tid;
            Oh[oo] = hh; Ol[oo] = ll;
        }
    }
}

// ---------------- head GEMM (N=35) ----------------
__global__ void head_gemm(const float* __restrict__ X, const float* __restrict__ W,
                          const float* __restrict__ bias, float* __restrict__ Lg)
{
    int r = blockIdx.x;
    __shared__ float xs[H];
    for (int j = threadIdx.x; j < H; j += blockDim.x) xs[j] = X[(size_t)r*H + j];
    __syncthreads();
    if (threadIdx.x < KK) {
        int k = threadIdx.x;
        float s = bias[k];
        for (int j = 0; j < H; j++) s += xs[j] * W[j*KK + k];
        Lg[r*KK + k] = s;
    }
}

// ---------------- CRF forward + gold score ----------------
__global__ void crf_forward_kernel(const float* __restrict__ logits,
                                   const int* __restrict__ mask,
                                   const int* __restrict__ labels,
                                   const float* __restrict__ trans,
                                   float* __restrict__ fwd, float* __restrict__ gold)
{
    int b = blockIdx.x;
    __shared__ float tr[KK*KK];
    __shared__ float alpha[KK];
    int tid = threadIdx.x;
    for (int i = tid; i < KK*KK; i += 64) tr[i] = trans[i];
    __syncthreads();
    int j = tid;
    if (j < KK) alpha[j] = tr[START_TAG*KK + j] + logits[(size_t)(b*TT)*KK + j];
    __syncthreads();
    for (int t = 1; t < TT; t++) {
        float nv = 0.f;
        if (j < KK) {
            float mxv = -1e30f;
            for (int i = 0; i < KK; i++) { float v = alpha[i] + tr[i*KK + j]; if (v > mxv) mxv = v; }
            float s = 0.f;
            for (int i = 0; i < KK; i++) s += expf(alpha[i] + tr[i*KK + j] - mxv);
            nv = mxv + logf(s) + logits[(size_t)(b*TT + t)*KK + j];
        }
        int keep = (mask[b*TT + t] != 0);
        __syncthreads();
        if (j < KK && keep) alpha[j] = nv;
        __syncthreads();
    }
    if (j == 0) {
        float mxv = -1e30f;
        for (int i = 0; i < KK; i++) { float v = alpha[i] + tr[i*KK + END_TAG]; if (v > mxv) mxv = v; }
        float s = 0.f;
        for (int i = 0; i < KK; i++) s += expf(alpha[i] + tr[i*KK + END_TAG] - mxv);
        fwd[b] = mxv + logf(s);

        int tag0 = labels[b*TT + 0];
        float sc = tr[START_TAG*KK + tag0] + logits[(size_t)(b*TT)*KK + tag0];
        int prev = tag0;
        int lengths = 0;
        for (int t = 0; t < TT; t++) lengths += (mask[b*TT + t] != 0);
        for (int t = 1; t < TT; t++) {
            int tg = labels[b*TT + t];
            float mt = (mask[b*TT + t] != 0) ? 1.f : 0.f;
            sc += (tr[prev*KK + tg] + logits[(size_t)(b*TT + t)*KK + tg]) * mt;
            prev = tg;
        }
        int li = lengths - 1; if (li < 0) li = 0; if (li > TT-1) li = TT-1;
        int last_tag = labels[b*TT + li];
        sc += tr[last_tag*KK + END_TAG];
        gold[b] = sc;
    }
}

__global__ void loss_kernel(const float* __restrict__ fwd, const float* __restrict__ gold,
                            float* __restrict__ out)
{
    if (threadIdx.x == 0 && blockIdx.x == 0) {
        float s = 0.f;
        for (int b = 0; b < BB; b++) s += fwd[b] - gold[b];
        out[0] = s / (float)BB;
    }
}

// ---------------- Viterbi ----------------
__global__ void viterbi_kernel(const float* __restrict__ logits,
                               const int* __restrict__ mask,
                               const float* __restrict__ trans,
                               int* __restrict__ bps,
                               float* __restrict__ out)
{
    int b = blockIdx.x;
    __shared__ float tr[KK*KK];
    __shared__ float alpha[KK];
    int tid = threadIdx.x;
    for (int i = tid; i < KK*KK; i += 64) tr[i] = trans[i];
    __syncthreads();
    int j = tid;
    if (j < KK) alpha[j] = tr[START_TAG*KK + j] + logits[(size_t)(b*TT)*KK + j];
    __syncthreads();
    for (int t = 1; t < TT; t++) {
        float vmax = -1e30f; int bp = 0;
        if (j < KK) {
            for (int i = 0; i < KK; i++) {
                float v = alpha[i] + tr[i*KK + j];
                if (v > vmax) { vmax = v; bp = i; }
            }
            vmax += logits[(size_t)(b*TT + t)*KK + j];
        }
        int keep = (mask[b*TT + t] != 0);
        __syncthreads();
        if (j < KK) {
            if (keep) alpha[j] = vmax;
            bps[((t-1)*BB + b)*KK + j] = keep ? bp : j;
        }
        __syncthreads();
    }
    if (j == 0) {
        float best = -1e30f; int cur = 0;
        for (int i = 0; i < KK; i++) {
            float v = alpha[i] + tr[i*KK + END_TAG];
            if (v > best) { best = v; cur = i; }
        }
        out[1 + b*TT + (TT-1)] = (float)cur;
        for (int tt = TT-2; tt >= 0; tt--) {
            cur = bps[(tt*BB + b)*KK + cur];
            out[1 + b*TT + tt] = (float)cur;
        }
    }
}

// ---------------- host orchestration ----------------
extern "C" void kernel_launch(void* const* d_in, const int* in_sizes, int n_in,
                              void* d_out, int out_size)
{
    const int*   ids  = (const int*)  d_in[0];
    const int*   msk  = (const int*)  d_in[1];
    const int*   seg  = (const int*)  d_in[2];
    const int*   lab  = (const int*)  d_in[3];
    const float* wemb = (const float*)d_in[4];
    const float* pemb = (const float*)d_in[5];
    const float* temb = (const float*)d_in[6];
    const float* eg   = (const float*)d_in[7];
    const float* eb   = (const float*)d_in[8];
    const float* Wq   = (const float*)d_in[9];
    const float* bq   = (const float*)d_in[10];
    const float* Wk   = (const float*)d_in[11];
    const float* bk   = (const float*)d_in[12];
    const float* Wv   = (const float*)d_in[13];
    const float* bv   = (const float*)d_in[14];
    const float* Wo   = (const float*)d_in[15];
    const float* bo   = (const float*)d_in[16];
    const float* ln1g = (const float*)d_in[17];
    const float* ln1b = (const float*)d_in[18];
    const float* W1   = (const float*)d_in[19];
    const float* b1   = (const float*)d_in[20];
    const float* W2   = (const float*)d_in[21];
    const float* b2   = (const float*)d_in[22];
    const float* ln2g = (const float*)d_in[23];
    const float* ln2b = (const float*)d_in[24];
    const float* Wh   = (const float*)d_in[25];
    const float* bh   = (const float*)d_in[26];
    const float* trn  = (const float*)d_in[27];
    float* out = (float*)d_out;

    float *px, *ptmp, *pqkv, *plog, *pfwd, *pgold, *pbqkv;
    int* pbp;
    __nv_bfloat16 *pxh, *pxl, *pch, *pcl, *pfh, *pfl;
    __nv_bfloat16 *pwqh, *pwql, *pwoh, *pwol, *pw1h, *pw1l, *pw2h, *pw2l;
    cudaGetSymbolAddress((void**)&px,    g_x);
    cudaGetSymbolAddress((void**)&ptmp,  g_tmp);
    cudaGetSymbolAddress((void**)&pqkv,  g_qkv);
    cudaGetSymbolAddress((void**)&plog,  g_logits);
    cudaGetSymbolAddress((void**)&pfwd,  g_fwd);
    cudaGetSymbolAddress((void**)&pgold, g_gold);
    cudaGetSymbolAddress((void**)&pbp,   g_bp);
    cudaGetSymbolAddress((void**)&pbqkv, g_bqkv);
    cudaGetSymbolAddress((void**)&pxh,   g_xh);
    cudaGetSymbolAddress((void**)&pxl,   g_xl);
    cudaGetSymbolAddress((void**)&pch,   g_ch);
    cudaGetSymbolAddress((void**)&pcl,   g_cl);
    cudaGetSymbolAddress((void**)&pfh,   g_fh);
    cudaGetSymbolAddress((void**)&pfl,   g_fl);
    cudaGetSymbolAddress((void**)&pwqh,  g_wqkv_h);
    cudaGetSymbolAddress((void**)&pwql,  g_wqkv_l);
    cudaGetSymbolAddress((void**)&pwoh,  g_wo_h);
    cudaGetSymbolAddress((void**)&pwol,  g_wo_l);
    cudaGetSymbolAddress((void**)&pw1h,  g_w1_h);
    cudaGetSymbolAddress((void**)&pw1l,  g_w1_l);
    cudaGetSymbolAddress((void**)&pw2h,  g_w2_h);
    cudaGetSymbolAddress((void**)&pw2l,  g_w2_l);

    const size_t att_smem = ATT_SMEM_FLOATS * sizeof(float);
    cudaFuncSetAttribute(attention_kernel,
                         cudaFuncAttributeMaxDynamicSharedMemorySize, (int)att_smem);
    cudaFuncSetAttribute(gemm_bf16_mma,
                         cudaFuncAttributeMaxDynamicSharedMemorySize, GEMM_SMEM);

    // ---- weight preprocessing (transpose + bf16 hi/lo split) ----
    dim3 tb(32, 8);
    pack_bias<<<LNUM, 256>>>(bq, bk, bv, pbqkv);
    wsplit<<<dim3(H/32, H/32, LNUM), tb>>>(Wq, pwqh,                 pwql,                 H, H,
                                           (size_t)H*H, (size_t)QKVN*H);
    wsplit<<<dim3(H/32, H/32, LNUM), tb>>>(Wk, pwqh + (size_t)H*H,   pwql + (size_t)H*H,   H, H,
                                           (size_t)H*H, (size_t)QKVN*H);
    wsplit<<<dim3(H/32, H/32, LNUM), tb>>>(Wv, pwqh + (size_t)2*H*H, pwql + (size_t)2*H*H, H, H,
                                           (size_t)H*H, (size_t)QKVN*H);
    wsplit<<<dim3(H/32, H/32, LNUM), tb>>>(Wo, pwoh, pwol, H, H, (size_t)H*H, (size_t)H*H);
    wsplit<<<dim3(H/32, FF/32, LNUM), tb>>>(W1, pw1h, pw1l, H, FF, (size_t)H*FF, (size_t)FF*H);
    wsplit<<<dim3(FF/32, H/32, LNUM), tb>>>(W2, pw2h, pw2l, FF, H, (size_t)FF*H, (size_t)H*FF);

    // ---- embedding (+split) ----
    embed_ln_kernel<<<ROWS, 256>>>(ids, seg, wemb, pemb, temb, eg, eb, px, pxh, pxl);

    for (int l = 0; l < LNUM; l++) {
        // QKV (fused, N=2304): fp32 out for attention
        gemm_bf16_mma<<<dim3(QKVN/BN, ROWS/BM), 256, GEMM_SMEM>>>(
            pxh, pxl, pwqh + (size_t)l*QKVN*H, pwql + (size_t)l*QKVN*H,
            pbqkv + (size_t)l*QKVN, pqkv, nullptr, nullptr, QKVN, H, 2);

        // attention: writes split ctx directly
        attention_kernel<<<dim3(NH, BB), 256, att_smem>>>(pqkv, msk, pch, pcl);

        // output proj: fp32 out (residual)
        gemm_bf16_mma<<<dim3(H/BN, ROWS/BM), 256, GEMM_SMEM>>>(
            pch, pcl, pwoh + (size_t)l*H*H, pwol + (size_t)l*H*H,
            bo + (size_t)l*H, ptmp, nullptr, nullptr, H, H, 2);
        add_ln_kernel<<<ROWS, 256>>>(px, ptmp, ln1g + (size_t)l*H, ln1b + (size_t)l*H,
                                     px, pxh, pxl);

        // FF1 (+GELU): split-only output (feeds FF2 directly)
        gemm_bf16_mma<<<dim3(FF/BN, ROWS/BM), 256, GEMM_SMEM>>>(
            pxh, pxl, pw1h + (size_t)l*FF*H, pw1l + (size_t)l*FF*H,
            b1 + (size_t)l*FF, nullptr, pfh, pfl, FF, H, 1 | 4);

        // FF2: fp32 out (residual)
        gemm_bf16_mma<<<dim3(H/BN, ROWS/BM), 256, GEMM_SMEM>>>(
            pfh, pfl, pw2h + (size_t)l*H*FF, pw2l + (size_t)l*H*FF,
            b2 + (size_t)l*H, ptmp, nullptr, nullptr, H, FF, 2);
        add_ln_kernel<<<ROWS, 256>>>(px, ptmp, ln2g + (size_t)l*H, ln2b + (size_t)l*H,
                                     px, pxh, pxl);
    }

    head_gemm<<<ROWS, 128>>>(px, Wh, bh, plog);
    crf_forward_kernel<<<BB, 64>>>(plog, msk, lab, trn, pfwd, pgold);
    loss_kernel<<<1, 32>>>(pfwd, pgold, out);
    viterbi_kernel<<<BB, 64>>>(plog, msk, trn, pbp, out);
}